// round 11
// baseline (speedup 1.0000x reference)
#include <cuda_runtime.h>
#include <cstdint>

typedef unsigned long long ull;

__constant__ float cCC[6]  = {0.f, 0.2f, 0.3f, 0.8f, (float)(8.0/9.0), 1.0f};
__constant__ float cBWv[6] = {(float)(35.0/384.0), 0.f, (float)(500.0/1113.0),
                              (float)(125.0/192.0), (float)(-2187.0/6784.0),
                              (float)(11.0/84.0)};

// ---- smem layout (float offsets) ----
#define oXs  0        /* [s:2][128] = 256 */
#define oA   256      /* [s:2][256] = 512 */
#define oHP  768      /* 2048: G1 [kq:4][s:2][256] / G2 [kq:8][s:2][128] (phase-disjoint) */
#define oPb  2816     /* [p:2][c:128 ull] = 512 floats (remote partial only) */
#define oScr 3328     /* 32 */
#define oTx  3360     /* 2 */
#define oDx  3362     /* 2 */
#define oLp  3364     /* 2 */
#define SMF  3368

__device__ __forceinline__ ull pk(float w) {
  ull r; asm("mov.b64 %0, {%1, %2};" : "=l"(r) : "f"(w), "f"(w)); return r;
}
__device__ __forceinline__ ull mk2(float a, float b) {
  ull r; asm("mov.b64 %0, {%1, %2};" : "=l"(r) : "f"(a), "f"(b)); return r;
}
__device__ __forceinline__ float lo32(ull v) { return __uint_as_float((unsigned)v); }
__device__ __forceinline__ float hi32(ull v) { return __uint_as_float((unsigned)(v >> 32)); }
__device__ __forceinline__ ull f2fma(ull a, ull b, ull c) {
  ull d; asm("fma.rn.f32x2 %0,%1,%2,%3;" : "=l"(d) : "l"(a), "l"(b), "l"(c)); return d;
}
__device__ __forceinline__ ull f2add(ull a, ull b) {
  ull d; asm("add.rn.f32x2 %0,%1,%2;" : "=l"(d) : "l"(a), "l"(b)); return d;
}
__device__ __forceinline__ ull f2mul(ull a, ull b) {
  ull d; asm("mul.rn.f32x2 %0,%1,%2;" : "=l"(d) : "l"(a), "l"(b)); return d;
}
__device__ __forceinline__ float wsum(float v) {
#pragma unroll
  for (int o = 16; o > 0; o >>= 1) v += __shfl_xor_sync(0xffffffffu, v, o);
  return v;
}
__device__ __forceinline__ uint32_t smem_u32(const void* p) {
  uint32_t a;
  asm("{.reg .u64 t; cvta.to.shared.u64 t, %1; cvt.u32.u64 %0, t;}" : "=r"(a) : "l"(p));
  return a;
}
__device__ __forceinline__ uint32_t mapa_u32(uint32_t addr, uint32_t rank) {
  uint32_t ra; asm("mapa.shared::cluster.u32 %0, %1, %2;" : "=r"(ra) : "r"(addr), "r"(rank));
  return ra;
}
__device__ __forceinline__ float ldcf(uint32_t addr, uint32_t rank) {
  uint32_t ra = mapa_u32(addr, rank);
  float v; asm volatile("ld.shared::cluster.f32 %0, [%1];" : "=f"(v) : "r"(ra)); return v;
}
__device__ __forceinline__ void csync() {
  asm volatile("barrier.cluster.arrive.aligned;" ::: "memory");
  asm volatile("barrier.cluster.wait.aligned;" ::: "memory");
}
__device__ __forceinline__ void mbar_init(uint32_t mb, unsigned cnt) {
  asm volatile("mbarrier.init.shared::cta.b64 [%0], %1;" :: "r"(mb), "r"(cnt) : "memory");
}
__device__ __forceinline__ void mbar_arm(uint32_t mb, unsigned tx) {
  asm volatile("mbarrier.arrive.expect_tx.shared::cta.b64 _, [%0], %1;"
               :: "r"(mb), "r"(tx) : "memory");
}
__device__ __forceinline__ void st_async64(uint32_t ra, ull v, uint32_t rmb) {
  asm volatile("st.async.shared::cluster.mbarrier::complete_tx::bytes.b64 [%0], %1, [%2];"
               :: "r"(ra), "l"(v), "r"(rmb) : "memory");
}
// CTA-scope acquire (canonical TMA/st.async consumer pattern)
__device__ __forceinline__ void waitp(uint32_t mb, unsigned ph) {
  unsigned done;
  asm volatile(
      "{\n\t.reg .pred p;\n\t"
      "mbarrier.try_wait.parity.acquire.cta.shared::cta.b64 p, [%1], %2;\n\t"
      "selp.u32 %0,1,0,p;\n\t}"
      : "=r"(done) : "r"(mb), "r"(ph) : "memory");
  while (!done) {
    asm volatile(
        "{\n\t.reg .pred p;\n\t"
        "mbarrier.try_wait.parity.acquire.cta.shared::cta.b64 p, [%1], %2, 0x989680;\n\t"
        "selp.u32 %0,1,0,p;\n\t}"
        : "=r"(done) : "r"(mb), "r"(ph) : "memory");
  }
}
__device__ __forceinline__ float ftanh(float x) {
  float e = __expf(2.f * x);
  return 1.f - __fdividef(2.f, e + 1.f);
}

// GEMM1: 256 out-cols, 2 samples, K=128. Thread (cg=t&63, kq=t>>6): cols
// 4cg..4cg+3, k in [32kq,32kq+32). src [s:2][128]; dst [kq:4][s:2][256].
__device__ __forceinline__ void gemm1(const ull (&w)[4][16],
                                      const float* __restrict__ src,
                                      float* __restrict__ dst, int kq, int cg) {
  const float* sp = src + (kq << 5);
  float* dp = dst + (kq << 9) + (cg << 2);
#pragma unroll
  for (int s = 0; s < 2; ++s) {
    ull a0 = 0, a1 = 0, a2 = 0, a3 = 0;
#pragma unroll
    for (int i = 0; i < 8; ++i) {
      ulonglong2 x = *(const ulonglong2*)(sp + s * 128 + (i << 2));
      a0 = f2fma(w[0][2 * i], x.x, a0); a0 = f2fma(w[0][2 * i + 1], x.y, a0);
      a1 = f2fma(w[1][2 * i], x.x, a1); a1 = f2fma(w[1][2 * i + 1], x.y, a1);
      a2 = f2fma(w[2][2 * i], x.x, a2); a2 = f2fma(w[2][2 * i + 1], x.y, a2);
      a3 = f2fma(w[3][2 * i], x.x, a3); a3 = f2fma(w[3][2 * i + 1], x.y, a3);
    }
    float4 r;
    r.x = lo32(a0) + hi32(a0);
    r.y = lo32(a1) + hi32(a1);
    r.z = lo32(a2) + hi32(a2);
    r.w = lo32(a3) + hi32(a3);
    *(float4*)(dp + s * 256) = r;
  }
}

// GEMM2: 128 out-cols, 2 samples, K=256 (local h). Thread (cg=t&31, kq=t>>5):
// cols 4cg..4cg+3, k in [32kq,32kq+32). src [s:2][256]; dst [kq:8][s:2][128].
__device__ __forceinline__ void gemm2(const ull (&w)[4][16],
                                      const float* __restrict__ src,
                                      float* __restrict__ dst, int kq, int cg) {
  const float* sp = src + (kq << 5);
  float* dp = dst + (kq << 8) + (cg << 2);
#pragma unroll
  for (int s = 0; s < 2; ++s) {
    ull a0 = 0, a1 = 0, a2 = 0, a3 = 0;
#pragma unroll
    for (int i = 0; i < 8; ++i) {
      ulonglong2 x = *(const ulonglong2*)(sp + s * 256 + (i << 2));
      a0 = f2fma(w[0][2 * i], x.x, a0); a0 = f2fma(w[0][2 * i + 1], x.y, a0);
      a1 = f2fma(w[1][2 * i], x.x, a1); a1 = f2fma(w[1][2 * i + 1], x.y, a1);
      a2 = f2fma(w[2][2 * i], x.x, a2); a2 = f2fma(w[2][2 * i + 1], x.y, a2);
      a3 = f2fma(w[3][2 * i], x.x, a3); a3 = f2fma(w[3][2 * i + 1], x.y, a3);
    }
    float4 r;
    r.x = lo32(a0) + hi32(a0);
    r.y = lo32(a1) + hi32(a1);
    r.z = lo32(a2) + hi32(a2);
    r.w = lo32(a3) + hi32(a3);
    *(float4*)(dp + s * 128) = r;
  }
}

__device__ __forceinline__ void rk_adv(int st, ull kacc, float dt,
    ull& k0, ull& k1, ull& k2, ull& k3, ull& k4, ull& y, ull& xs) {
  ull acc;
  switch (st) {
    case 0:
      k0 = kacc; acc = f2mul(pk(0.2f), k0);
      xs = f2fma(pk(dt), acc, y); break;
    case 1:
      k1 = kacc;
      acc = f2mul(pk(0.075f), k0);
      acc = f2fma(pk(0.225f), k1, acc);
      xs = f2fma(pk(dt), acc, y); break;
    case 2:
      k2 = kacc;
      acc = f2mul(pk((float)(44.0 / 45.0)), k0);
      acc = f2fma(pk((float)(-56.0 / 15.0)), k1, acc);
      acc = f2fma(pk((float)(32.0 / 9.0)), k2, acc);
      xs = f2fma(pk(dt), acc, y); break;
    case 3:
      k3 = kacc;
      acc = f2mul(pk((float)(19372.0 / 6561.0)), k0);
      acc = f2fma(pk((float)(-25360.0 / 2187.0)), k1, acc);
      acc = f2fma(pk((float)(64448.0 / 6561.0)), k2, acc);
      acc = f2fma(pk((float)(-212.0 / 729.0)), k3, acc);
      xs = f2fma(pk(dt), acc, y); break;
    case 4:
      k4 = kacc;
      acc = f2mul(pk((float)(9017.0 / 3168.0)), k0);
      acc = f2fma(pk((float)(-355.0 / 33.0)), k1, acc);
      acc = f2fma(pk((float)(46732.0 / 5247.0)), k2, acc);
      acc = f2fma(pk((float)(49.0 / 176.0)), k3, acc);
      acc = f2fma(pk((float)(-5103.0 / 18656.0)), k4, acc);
      xs = f2fma(pk(dt), acc, y); break;
    default:
      acc = f2mul(pk((float)(35.0 / 384.0)), k0);
      acc = f2fma(pk((float)(500.0 / 1113.0)), k2, acc);
      acc = f2fma(pk((float)(125.0 / 192.0)), k3, acc);
      acc = f2fma(pk((float)(-2187.0 / 6784.0)), k4, acc);
      acc = f2fma(pk((float)(11.0 / 84.0)), kacc, acc);
      y = f2fma(pk(dt), acc, y);
      xs = y; break;
  }
}

__global__ void __launch_bounds__(256, 1) __cluster_dims__(2, 1, 1)
vino_kernel(const float* __restrict__ x0g, const float* __restrict__ W1g,
            const float* __restrict__ b1g, const float* __restrict__ u1g,
            const float* __restrict__ W2g, const float* __restrict__ b2g,
            const int* __restrict__ nsp, float* __restrict__ out, int B) {
  __shared__ __align__(16) float sm[SMF];
  __shared__ __align__(8) unsigned long long smbar[2];
  const int t = threadIdx.x;
  const int w = t >> 5, lane = t & 31;
  const int cg1 = t & 63, kq1 = t >> 6;   // GEMM1 tiling
  const int cg2 = t & 31, kq2 = t >> 5;   // GEMM2 tiling
  const int tau = t;                      // tanh: local h-col
  const int c = t & 127;                  // RK element (t<128)
  uint32_t rank; asm("mov.u32 %0, %%cluster_ctarank;" : "=r"(rank));
  const uint32_t peer = rank ^ 1u;
  const int hbase = (int)rank << 8;       // 256 h-cols per CTA
  const int sb = (blockIdx.x >> 1) << 1;  // 2 samples per cluster

  // ---- persistent k-pair-packed weights: 64 ull each GEMM ----
  ull w1p[4][16], w2p[4][16];
#pragma unroll
  for (int j = 0; j < 4; ++j)
#pragma unroll
    for (int i = 0; i < 16; ++i) {
      const int k0 = (kq1 << 5) + 2 * i;
      const int col1 = hbase + 4 * cg1 + j;
      w1p[j][i] = mk2(W1g[k0 * 512 + col1], W1g[(k0 + 1) * 512 + col1]);
      const int r0 = hbase + (kq2 << 5) + 2 * i;
      const int col2 = 4 * cg2 + j;
      w2p[j][i] = mk2(W2g[r0 * 128 + col2], W2g[(r0 + 1) * 128 + col2]);
    }

  // ---- per-thread constants ----
  const float b1r = b1g[hbase + tau];
  const float u1r = u1g[hbase + tau];
  const ull b2p = pk(b2g[c]);
  float mr = 0.f;
#pragma unroll 4
  for (int i = 0; i < 128; ++i)
    mr = fmaf(W1g[i * 512 + hbase + tau], W2g[(hbase + tau) * 128 + i], mr);

  // ---- state (t<128): y = (sample0, sample1) at element col c ----
  ull y = 0, xs = 0;
  if (t < 128) {
    y = mk2(x0g[(sb + 0) * 128 + c], x0g[(sb + 1) * 128 + c]);
    xs = y;
    sm[oXs + c] = lo32(xs);
    sm[oXs + 128 + c] = hi32(xs);
  }

  // ---- mbarriers + peer addresses ----
  const uint32_t sbase = smem_u32(sm);
  const uint32_t mb0 = smem_u32(&smbar[0]);
  if (t == 0) {
    mbar_init(mb0, 1); mbar_init(mb0 + 8, 1);
    mbar_arm(mb0, 1024u); mbar_arm(mb0 + 8, 1024u);  // 128 x 8B per stage
  }
  const uint32_t rdat0 = mapa_u32(sbase + (uint32_t)(oPb + 2 * c) * 4u, peer);
  const uint32_t rmb0  = mapa_u32(mb0, peer);

  // ---- log p(x0) ----
  if (t < 128) {
    float s0 = wsum(lo32(y) * lo32(y)), s1 = wsum(hi32(y) * hi32(y));
    if (lane == 0) { sm[oScr + w * 2] = s0; sm[oScr + w * 2 + 1] = s1; }
  }
  __syncthreads();
  if (t < 2) {
    float ss = 0.f;
#pragma unroll
    for (int q = 0; q < 4; ++q) ss += sm[oScr + q * 2 + t];
    sm[oLp + t] = -0.5f * ss - 117.6241322501981f;  // 64*log(2*pi)
  }
  csync();  // arming + smem init visible cluster-wide

  const int ns = *nsp;
  const float dt = 1.0f / (float)ns;
  ull ks0 = 0, ks1 = 0, ks2 = 0, ks3 = 0, ks4 = 0;
  ull acc_tr = 0, acc_dot = 0;
  unsigned par0 = 0, par1 = 0;

  for (int step = 0; step < ns; ++step) {
    const float tstep = (float)step * dt;
#pragma unroll 1
    for (int stage = 0; stage < 6; ++stage) {
      const float coef = dt * cBWv[stage];
      const float tcur = tstep + cCC[stage] * dt;
      const int p = stage & 1;

      __syncthreads();                       // S_A: oXs visible
      gemm1(w1p, sm + oXs, sm + oHP, kq1, cg1);
      __syncthreads();                       // S_B

      // tanh + trace: every thread owns one local h-col (both samples)
      {
        const float bias = fmaf(tcur, u1r, b1r);
        float h0 = bias, h1 = bias;
#pragma unroll
        for (int q = 0; q < 4; ++q) {
          h0 += sm[oHP + (q << 9) + tau];
          h1 += sm[oHP + (q << 9) + 256 + tau];
        }
        float a0 = ftanh(h0), a1 = ftanh(h1);
        sm[oA + tau] = a0;
        sm[oA + 256 + tau] = a1;
        acc_tr = f2fma(mk2((1.f - a0 * a0) * mr, (1.f - a1 * a1) * mr),
                       pk(coef), acc_tr);
      }
      __syncthreads();                       // S_C
      gemm2(w2p, sm + oA, sm + oHP, kq2, cg2);
      __syncthreads();                       // S_D

      if (t < 128) {
        // fold local partial (register), push to the single peer
        float v0 = 0.f, v1 = 0.f;
#pragma unroll
        for (int q = 0; q < 8; ++q) {
          v0 += sm[oHP + (q << 8) + c];
          v1 += sm[oHP + (q << 8) + 128 + c];
        }
        ull vloc = mk2(v0, v1);
        st_async64(rdat0 + ((uint32_t)p << 10), vloc, rmb0 + ((uint32_t)p << 3));

        // wait for peer's 1KB, re-arm
        {
          const uint32_t lmb = mb0 + (p << 3);
          unsigned ph = p ? par1 : par0;
          waitp(lmb, ph);
          if (p) par1 ^= 1; else par0 ^= 1;
          if (t == 0) mbar_arm(lmb, 1024u);
        }

        // assemble dxdt = local + remote + b2; dot; RK advance
        ull kacc = f2add(vloc, ((const ull*)(sm + oPb))[p * 128 + c]);
        kacc = f2add(kacc, b2p);
        acc_dot = f2fma(f2mul(xs, kacc), pk(coef), acc_dot);
        rk_adv(stage, kacc, dt, ks0, ks1, ks2, ks3, ks4, y, xs);
        sm[oXs + c] = lo32(xs);
        sm[oXs + 128 + c] = hi32(xs);
      }
    }
  }

  // ---- outputs: z ----
  if (t < 128) {
    out[(sb + 0) * 128 + c] = lo32(y);
    out[(sb + 1) * 128 + c] = hi32(y);
  }

  // ---- final reductions ----
  {
    float tlo = wsum(lo32(acc_tr)), thi = wsum(hi32(acc_tr));
    if (lane == 0) { sm[oScr + w * 2] = tlo; sm[oScr + w * 2 + 1] = thi; }
  }
  __syncthreads();
  if (t < 2) {
    float T = 0.f;
#pragma unroll
    for (int q = 0; q < 8; ++q) T += sm[oScr + q * 2 + t];
    sm[oTx + t] = T;
  }
  __syncthreads();
  if (t < 128) {
    float dlo = wsum(lo32(acc_dot)), dhi = wsum(hi32(acc_dot));
    if (lane == 0) { sm[oScr + 16 + w * 2] = dlo; sm[oScr + 16 + w * 2 + 1] = dhi; }
  }
  __syncthreads();
  if (t < 2) {
    float D = 0.f;
#pragma unroll
    for (int q = 0; q < 4; ++q) D += sm[oScr + 16 + q * 2 + t];
    sm[oDx + t] = D;
  }
  csync();
  if (t < 2) {
    const uint32_t ta = smem_u32(&sm[oTx + t]);
    float T2 = ldcf(ta, 0) + ldcf(ta, 1);
    out[B * 128 + sb + t]     = sm[oLp + t] - T2;   // log_px
    out[B * 128 + B + sb + t] = sm[oDx + t] - T2;   // kl
  }
  csync();  // keep smem alive until peer finishes remote reads
}

extern "C" void kernel_launch(void* const* d_in, const int* in_sizes, int n_in,
                              void* d_out, int out_size) {
  const float* x0 = (const float*)d_in[0];
  const float* W1 = (const float*)d_in[1];
  const float* b1 = (const float*)d_in[2];
  const float* u1 = (const float*)d_in[3];
  const float* W2 = (const float*)d_in[4];
  const float* b2 = (const float*)d_in[5];
  const int*   ns = (const int*)d_in[6];
  float* out = (float*)d_out;
  int B = in_sizes[0] / 128;
  vino_kernel<<<B, 256>>>(x0, W1, b1, u1, W2, b2, ns, out, B);
}

// round 12
// speedup vs baseline: 2.2122x; 2.2122x over previous
#include <cuda_runtime.h>
#include <cstdint>

typedef unsigned long long ull;

__constant__ float cCC[6]  = {0.f, 0.2f, 0.3f, 0.8f, (float)(8.0/9.0), 1.0f};
__constant__ float cBWv[6] = {(float)(35.0/384.0), 0.f, (float)(500.0/1113.0),
                              (float)(125.0/192.0), (float)(-2187.0/6784.0),
                              (float)(11.0/84.0)};

// ---- smem layout (float offsets) ----
#define oXs  0        /* 512: per-sample rows [s:4][128] */
#define oA   512      /* 512 */
#define oHP  1024     /* 2048: G1 [kq:4][s:4][128]; G2 halves [kq:4][s2:2][128] x2 */
#define oPb  3072     /* 4096: exchange [p:2][rank:4][pr:2][c:128] ull */
#define oScr 7168     /* 32 */
#define oTx  7200     /* 4 */
#define oLp  7204     /* 4 */
#define SMF  7208

__device__ __forceinline__ ull pk(float w) {
  ull r; asm("mov.b64 %0, {%1, %2};" : "=l"(r) : "f"(w), "f"(w)); return r;
}
__device__ __forceinline__ ull mk2(float a, float b) {
  ull r; asm("mov.b64 %0, {%1, %2};" : "=l"(r) : "f"(a), "f"(b)); return r;
}
__device__ __forceinline__ float lo32(ull v) { return __uint_as_float((unsigned)v); }
__device__ __forceinline__ float hi32(ull v) { return __uint_as_float((unsigned)(v >> 32)); }
__device__ __forceinline__ ull f2fma(ull a, ull b, ull c) {
  ull d; asm("fma.rn.f32x2 %0,%1,%2,%3;" : "=l"(d) : "l"(a), "l"(b), "l"(c)); return d;
}
__device__ __forceinline__ ull f2add(ull a, ull b) {
  ull d; asm("add.rn.f32x2 %0,%1,%2;" : "=l"(d) : "l"(a), "l"(b)); return d;
}
__device__ __forceinline__ ull f2mul(ull a, ull b) {
  ull d; asm("mul.rn.f32x2 %0,%1,%2;" : "=l"(d) : "l"(a), "l"(b)); return d;
}
__device__ __forceinline__ float wsum(float v) {
#pragma unroll
  for (int o = 16; o > 0; o >>= 1) v += __shfl_xor_sync(0xffffffffu, v, o);
  return v;
}
__device__ __forceinline__ uint32_t smem_u32(const void* p) {
  uint32_t a;
  asm("{.reg .u64 t; cvta.to.shared.u64 t, %1; cvt.u32.u64 %0, t;}" : "=r"(a) : "l"(p));
  return a;
}
__device__ __forceinline__ uint32_t mapa_u32(uint32_t addr, uint32_t rank) {
  uint32_t ra; asm("mapa.shared::cluster.u32 %0, %1, %2;" : "=r"(ra) : "r"(addr), "r"(rank));
  return ra;
}
__device__ __forceinline__ float ldcf(uint32_t addr, uint32_t rank) {
  uint32_t ra = mapa_u32(addr, rank);
  float v; asm volatile("ld.shared::cluster.f32 %0, [%1];" : "=f"(v) : "r"(ra)); return v;
}
__device__ __forceinline__ void csync() {
  asm volatile("barrier.cluster.arrive.aligned;" ::: "memory");
  asm volatile("barrier.cluster.wait.aligned;" ::: "memory");
}
__device__ __forceinline__ void mbar_init(uint32_t mb, unsigned cnt) {
  asm volatile("mbarrier.init.shared::cta.b64 [%0], %1;" :: "r"(mb), "r"(cnt) : "memory");
}
__device__ __forceinline__ void mbar_arm(uint32_t mb, unsigned tx) {
  asm volatile("mbarrier.arrive.expect_tx.shared::cta.b64 _, [%0], %1;"
               :: "r"(mb), "r"(tx) : "memory");
}
__device__ __forceinline__ void st_async64(uint32_t ra, ull v, uint32_t rmb) {
  asm volatile("st.async.shared::cluster.mbarrier::complete_tx::bytes.b64 [%0], %1, [%2];"
               :: "r"(ra), "l"(v), "r"(rmb) : "memory");
}
// CTA-scope acquire: sufficient for async-proxy (st.async) data landing in OUR smem.
__device__ __forceinline__ void waitp(uint32_t mb, unsigned ph) {
  unsigned done;
  asm volatile(
      "{\n\t.reg .pred p;\n\t"
      "mbarrier.try_wait.parity.acquire.cta.shared::cta.b64 p, [%1], %2;\n\t"
      "selp.u32 %0,1,0,p;\n\t}"
      : "=r"(done) : "r"(mb), "r"(ph) : "memory");
  while (!done) {
    asm volatile(
        "{\n\t.reg .pred p;\n\t"
        "mbarrier.try_wait.parity.acquire.cta.shared::cta.b64 p, [%1], %2, 0x989680;\n\t"
        "selp.u32 %0,1,0,p;\n\t}"
        : "=r"(done) : "r"(mb), "r"(ph) : "memory");
  }
}
__device__ __forceinline__ float ftanh(float x) {
  float e = __expf(2.f * x);
  return 1.f - __fdividef(2.f, e + 1.f);
}

// GEMM quarter (4 samples): thread (cq=t&63, kq=t>>6) computes cols {cq,cq+64}
// over k in [32kq,32kq+32). src: per-sample rows [s:4][128]; dst [kq][s:4][128].
__device__ __forceinline__ void gemm_q(const ull (&w)[2][16],
                                       const float* __restrict__ src,
                                       float* __restrict__ dst, int kq, int cq) {
  ull a00 = 0, a01 = 0, a02 = 0, a03 = 0;
  ull a10 = 0, a11 = 0, a12 = 0, a13 = 0;
  const float* s0 = src + (kq << 5);
#pragma unroll
  for (int i = 0; i < 8; ++i) {
    ulonglong2 x0 = *(const ulonglong2*)(s0 + 0 * 128 + (i << 2));
    ulonglong2 x1 = *(const ulonglong2*)(s0 + 1 * 128 + (i << 2));
    ulonglong2 x2 = *(const ulonglong2*)(s0 + 2 * 128 + (i << 2));
    ulonglong2 x3 = *(const ulonglong2*)(s0 + 3 * 128 + (i << 2));
    ull w0a = w[0][2 * i], w0b = w[0][2 * i + 1];
    ull w1a = w[1][2 * i], w1b = w[1][2 * i + 1];
    a00 = f2fma(w0a, x0.x, a00); a00 = f2fma(w0b, x0.y, a00);
    a01 = f2fma(w0a, x1.x, a01); a01 = f2fma(w0b, x1.y, a01);
    a02 = f2fma(w0a, x2.x, a02); a02 = f2fma(w0b, x2.y, a02);
    a03 = f2fma(w0a, x3.x, a03); a03 = f2fma(w0b, x3.y, a03);
    a10 = f2fma(w1a, x0.x, a10); a10 = f2fma(w1b, x0.y, a10);
    a11 = f2fma(w1a, x1.x, a11); a11 = f2fma(w1b, x1.y, a11);
    a12 = f2fma(w1a, x2.x, a12); a12 = f2fma(w1b, x2.y, a12);
    a13 = f2fma(w1a, x3.x, a13); a13 = f2fma(w1b, x3.y, a13);
  }
  float* d0 = dst + (kq << 9) + cq;
  d0[0 * 128]      = lo32(a00) + hi32(a00);
  d0[1 * 128]      = lo32(a01) + hi32(a01);
  d0[2 * 128]      = lo32(a02) + hi32(a02);
  d0[3 * 128]      = lo32(a03) + hi32(a03);
  d0[0 * 128 + 64] = lo32(a10) + hi32(a10);
  d0[1 * 128 + 64] = lo32(a11) + hi32(a11);
  d0[2 * 128 + 64] = lo32(a12) + hi32(a12);
  d0[3 * 128 + 64] = lo32(a13) + hi32(a13);
}

// GEMM quarter (2 samples): same tiling, rows s,s+1 at src; dst [kq][s2:2][128].
__device__ __forceinline__ void gemm_q2(const ull (&w)[2][16],
                                        const float* __restrict__ src,
                                        float* __restrict__ dst, int kq, int cq) {
  ull a00 = 0, a01 = 0, a10 = 0, a11 = 0;
  const float* s0 = src + (kq << 5);
#pragma unroll
  for (int i = 0; i < 8; ++i) {
    ulonglong2 x0 = *(const ulonglong2*)(s0 + (i << 2));
    ulonglong2 x1 = *(const ulonglong2*)(s0 + 128 + (i << 2));
    ull w0a = w[0][2 * i], w0b = w[0][2 * i + 1];
    ull w1a = w[1][2 * i], w1b = w[1][2 * i + 1];
    a00 = f2fma(w0a, x0.x, a00); a00 = f2fma(w0b, x0.y, a00);
    a01 = f2fma(w0a, x1.x, a01); a01 = f2fma(w0b, x1.y, a01);
    a10 = f2fma(w1a, x0.x, a10); a10 = f2fma(w1b, x0.y, a10);
    a11 = f2fma(w1a, x1.x, a11); a11 = f2fma(w1b, x1.y, a11);
  }
  float* d0 = dst + (kq << 8) + cq;
  d0[0]        = lo32(a00) + hi32(a00);
  d0[128]      = lo32(a01) + hi32(a01);
  d0[64]       = lo32(a10) + hi32(a10);
  d0[128 + 64] = lo32(a11) + hi32(a11);
}

__global__ void __launch_bounds__(256, 1) __cluster_dims__(4, 1, 1)
vino_kernel(const float* __restrict__ x0g, const float* __restrict__ W1g,
            const float* __restrict__ b1g, const float* __restrict__ u1g,
            const float* __restrict__ W2g, const float* __restrict__ b2g,
            const int* __restrict__ nsp, float* __restrict__ out, int B) {
  __shared__ __align__(16) float sm[SMF];
  __shared__ __align__(8) unsigned long long smbar[2];
  const int t = threadIdx.x;
  const int w = t >> 5, lane = t & 31;
  const int cq = t & 63, kq = t >> 6;       // GEMM tiling
  const int c = t & 127, pr = t >> 7;       // epilogue: element col c, pair pr
  const int s0i = 2 * pr, s1i = 2 * pr + 1;
  uint32_t rank; asm("mov.u32 %0, %%cluster_ctarank;" : "=r"(rank));
  const int hbase = (int)rank << 7;
  const int sb = (blockIdx.x >> 2) << 2;

  // ---- persistent k-pair-packed weight registers ----
  ull w1p[2][16], w2p[2][16];
#pragma unroll
  for (int i = 0; i < 16; ++i) {
    const int kk = (kq << 5) + 2 * i;
    w1p[0][i] = mk2(W1g[kk * 512 + hbase + cq],      W1g[(kk + 1) * 512 + hbase + cq]);
    w1p[1][i] = mk2(W1g[kk * 512 + hbase + cq + 64], W1g[(kk + 1) * 512 + hbase + cq + 64]);
    w2p[0][i] = mk2(W2g[(hbase + kk) * 128 + cq],      W2g[(hbase + kk + 1) * 128 + cq]);
    w2p[1][i] = mk2(W2g[(hbase + kk) * 128 + cq + 64], W2g[(hbase + kk + 1) * 128 + cq + 64]);
  }

  // ---- per-thread constants ----
  const float b1r = b1g[hbase + c];
  const float u1r = u1g[hbase + c];
  const ull b2p = pk(b2g[c]);
  float mr = 0.f;
#pragma unroll 4
  for (int i = 0; i < 128; ++i)
    mr = fmaf(W1g[i * 512 + hbase + c], W2g[(hbase + c) * 128 + i], mr);

  // ---- state init ----
  ull y = mk2(x0g[(sb + s0i) * 128 + c], x0g[(sb + s1i) * 128 + c]);
  ull xs = y;
  sm[oXs + s0i * 128 + c] = lo32(xs);
  sm[oXs + s1i * 128 + c] = hi32(xs);

  // ---- mbarriers + remote push addresses (p=0 base) ----
  const uint32_t sbase = smem_u32(sm);
  const uint32_t mb0 = smem_u32(&smbar[0]);
  if (t == 0) {
    mbar_init(mb0, 1); mbar_init(mb0 + 8, 1);
    mbar_arm(mb0, 6144u); mbar_arm(mb0 + 8, 6144u);  // 3 remote ranks x 2KB
  }
  // my slot in peer j's buffer: oPb + 2*((rank*2 + pr)*128 + c)
  uint32_t rdat[3], rmb[3];
  {
    const uint32_t loff =
        sbase + (uint32_t)(oPb + 2 * (((int)rank * 2 + pr) * 128 + c)) * 4u;
    int j = 0;
#pragma unroll
    for (uint32_t r = 0; r < 4; ++r) {
      if (r != rank) {
        rdat[j] = mapa_u32(loff, r);
        rmb[j]  = mapa_u32(mb0, r);
        ++j;
      }
    }
  }

  // ---- log p(x0) ----
  {
    float q0 = lo32(y), q1 = hi32(y);
    float ss0 = wsum(q0 * q0), ss1 = wsum(q1 * q1);
    if (lane == 0) { sm[oScr + w * 2] = ss0; sm[oScr + w * 2 + 1] = ss1; }
  }
  __syncthreads();
  if (t < 4) {
    const int gg = t >> 1, sp = t & 1;
    float ss = 0.f;
#pragma unroll
    for (int q = 0; q < 4; ++q) ss += sm[oScr + ((4 * gg + q) << 1) + sp];
    sm[oLp + t] = -0.5f * ss - 117.6241322501981f;  // 64*log(2*pi)
  }
  csync();  // arming + smem init visible cluster-wide

  const int ns = *nsp;
  const float dt = 1.0f / (float)ns;
  ull ks0 = 0, ks1 = 0, ks2 = 0, ks3 = 0, ks4 = 0;
  float tr0 = 0.f, tr1 = 0.f;
  ull acc_dot = 0;
  unsigned par0 = 0, par1 = 0;

  for (int step = 0; step < ns; ++step) {
    const float tstep = (float)step * dt;
#pragma unroll 1
    for (int stage = 0; stage < 6; ++stage) {
      const float coef = dt * cBWv[stage];
      const float tcur = tstep + cCC[stage] * dt;
      const int p = stage & 1;
      const uint32_t dof = (uint32_t)p << 13;   // parity byte offset in oPb
      const uint32_t mof = (uint32_t)p << 3;

      __syncthreads();                       // S_A: oXs visible
      gemm_q(w1p, sm + oXs, sm + oHP, kq, cq);
      __syncthreads();                       // S_B

      // tanh + trace
      {
        const float bias = fmaf(tcur, u1r, b1r);
        float h0 = (sm[oHP + s0i * 128 + c]        + sm[oHP + 512 + s0i * 128 + c]) +
                   (sm[oHP + 1024 + s0i * 128 + c] + sm[oHP + 1536 + s0i * 128 + c]) + bias;
        float h1 = (sm[oHP + s1i * 128 + c]        + sm[oHP + 512 + s1i * 128 + c]) +
                   (sm[oHP + 1024 + s1i * 128 + c] + sm[oHP + 1536 + s1i * 128 + c]) + bias;
        float a0 = ftanh(h0), a1 = ftanh(h1);
        sm[oA + s0i * 128 + c] = a0;
        sm[oA + s1i * 128 + c] = a1;
        tr0 = fmaf((1.f - a0 * a0) * mr, coef, tr0);
        tr1 = fmaf((1.f - a1 * a1) * mr, coef, tr1);
      }
      __syncthreads();                       // S_C

      // GEMM2 first half: samples 0,1 -> HPa at oHP
      gemm_q2(w2p, sm + oA, sm + oHP, kq, cq);
      __syncthreads();                       // S_D1

      ull vloc = 0;
      if (pr == 0) {
        // fold pr0 + early push (flight overlaps second half-GEMM)
        float v0 = (sm[oHP + c]       + sm[oHP + 256 + c]) +
                   (sm[oHP + 512 + c] + sm[oHP + 768 + c]);
        float v1 = (sm[oHP + 128 + c]       + sm[oHP + 256 + 128 + c]) +
                   (sm[oHP + 512 + 128 + c] + sm[oHP + 768 + 128 + c]);
        vloc = mk2(v0, v1);
        st_async64(rdat[0] + dof, vloc, rmb[0] + mof);
        st_async64(rdat[1] + dof, vloc, rmb[1] + mof);
        st_async64(rdat[2] + dof, vloc, rmb[2] + mof);
      }

      // GEMM2 second half: samples 2,3 -> HPb at oHP+1024
      gemm_q2(w2p, sm + oA + 256, sm + oHP + 1024, kq, cq);
      __syncthreads();                       // S_D2

      if (pr == 1) {
        float v0 = (sm[oHP + 1024 + c]       + sm[oHP + 1280 + c]) +
                   (sm[oHP + 1536 + c] + sm[oHP + 1792 + c]);
        float v1 = (sm[oHP + 1024 + 128 + c]       + sm[oHP + 1280 + 128 + c]) +
                   (sm[oHP + 1536 + 128 + c] + sm[oHP + 1792 + 128 + c]);
        vloc = mk2(v0, v1);
        st_async64(rdat[0] + dof, vloc, rmb[0] + mof);
        st_async64(rdat[1] + dof, vloc, rmb[1] + mof);
        st_async64(rdat[2] + dof, vloc, rmb[2] + mof);
      }

      // wait for 6KB from the 3 remote ranks, re-arm
      {
        const uint32_t lmb = mb0 + (p << 3);
        unsigned ph = p ? par1 : par0;
        waitp(lmb, ph);
        if (p) par1 ^= 1; else par0 ^= 1;
        if (t == 0) mbar_arm(lmb, 6144u);
      }

      // assemble dxdt = vloc + 3 remote partials + b2; dot; RK advance
      {
        const float* pb = sm + oPb + (p << 11);
        ull kacc = vloc;
#pragma unroll
        for (int r = 0; r < 4; ++r) {
          if (r != (int)rank)
            kacc = f2add(kacc, *(const ull*)(pb + 2 * ((r * 2 + pr) * 128 + c)));
        }
        kacc = f2add(kacc, b2p);
        acc_dot = f2fma(f2mul(xs, kacc), pk(coef), acc_dot);
        ull acc;
        switch (stage) {
          case 0:
            ks0 = kacc;
            acc = f2mul(pk(0.2f), ks0);
            xs = f2fma(pk(dt), acc, y);
            break;
          case 1:
            ks1 = kacc;
            acc = f2mul(pk(0.075f), ks0);
            acc = f2fma(pk(0.225f), ks1, acc);
            xs = f2fma(pk(dt), acc, y);
            break;
          case 2:
            ks2 = kacc;
            acc = f2mul(pk((float)(44.0 / 45.0)), ks0);
            acc = f2fma(pk((float)(-56.0 / 15.0)), ks1, acc);
            acc = f2fma(pk((float)(32.0 / 9.0)), ks2, acc);
            xs = f2fma(pk(dt), acc, y);
            break;
          case 3:
            ks3 = kacc;
            acc = f2mul(pk((float)(19372.0 / 6561.0)), ks0);
            acc = f2fma(pk((float)(-25360.0 / 2187.0)), ks1, acc);
            acc = f2fma(pk((float)(64448.0 / 6561.0)), ks2, acc);
            acc = f2fma(pk((float)(-212.0 / 729.0)), ks3, acc);
            xs = f2fma(pk(dt), acc, y);
            break;
          case 4:
            ks4 = kacc;
            acc = f2mul(pk((float)(9017.0 / 3168.0)), ks0);
            acc = f2fma(pk((float)(-355.0 / 33.0)), ks1, acc);
            acc = f2fma(pk((float)(46732.0 / 5247.0)), ks2, acc);
            acc = f2fma(pk((float)(49.0 / 176.0)), ks3, acc);
            acc = f2fma(pk((float)(-5103.0 / 18656.0)), ks4, acc);
            xs = f2fma(pk(dt), acc, y);
            break;
          default:
            acc = f2mul(pk((float)(35.0 / 384.0)), ks0);
            acc = f2fma(pk((float)(500.0 / 1113.0)), ks2, acc);
            acc = f2fma(pk((float)(125.0 / 192.0)), ks3, acc);
            acc = f2fma(pk((float)(-2187.0 / 6784.0)), ks4, acc);
            acc = f2fma(pk((float)(11.0 / 84.0)), kacc, acc);
            y = f2fma(pk(dt), acc, y);
            xs = y;
            break;
        }
        sm[oXs + s0i * 128 + c] = lo32(xs);
        sm[oXs + s1i * 128 + c] = hi32(xs);
      }
    }
  }

  // ---- outputs: z ----
  out[(sb + s0i) * 128 + c] = lo32(y);
  out[(sb + s1i) * 128 + c] = hi32(y);

  // ---- final reductions: trace (cross-CTA) and dot (local) ----
  {
    float tlo = wsum(tr0), thi = wsum(tr1);
    float dlo = wsum(lo32(acc_dot)), dhi = wsum(hi32(acc_dot));
    if (lane == 0) {
      sm[oScr + w * 4 + 0] = tlo; sm[oScr + w * 4 + 1] = thi;
      sm[oScr + w * 4 + 2] = dlo; sm[oScr + w * 4 + 3] = dhi;
    }
  }
  __syncthreads();
  if (t < 4) {
    const int gg = t >> 1, sp = t & 1;
    float T = 0.f, D = 0.f;
#pragma unroll
    for (int q = 0; q < 4; ++q) {
      T += sm[oScr + (4 * gg + q) * 4 + sp];
      D += sm[oScr + (4 * gg + q) * 4 + 2 + sp];
    }
    sm[oTx + t] = T;
    sm[oScr + t] = D;  // reuse scratch (post-sync)
  }
  csync();
  if (t < 4) {
    const uint32_t ta = smem_u32(&sm[oTx + t]);
    float T4 = 0.f;
#pragma unroll
    for (uint32_t r = 0; r < 4; ++r) T4 += ldcf(ta, r);
    out[B * 128 + sb + t]     = sm[oLp + t] - T4;       // log_px
    out[B * 128 + B + sb + t] = sm[oScr + t] - T4;      // kl
  }
  csync();  // keep smem alive until peers finish remote reads
}

extern "C" void kernel_launch(void* const* d_in, const int* in_sizes, int n_in,
                              void* d_out, int out_size) {
  const float* x0 = (const float*)d_in[0];
  const float* W1 = (const float*)d_in[1];
  const float* b1 = (const float*)d_in[2];
  const float* u1 = (const float*)d_in[3];
  const float* W2 = (const float*)d_in[4];
  const float* b2 = (const float*)d_in[5];
  const int*   ns = (const int*)d_in[6];
  float* out = (float*)d_out;
  int B = in_sizes[0] / 128;
  vino_kernel<<<B, 256>>>(x0, W1, b1, u1, W2, b2, ns, out, B);
}